// round 1
// baseline (speedup 1.0000x reference)
#include <cuda_runtime.h>
#include <cuda_bf16.h>

// ---------------- constants ----------------
#define BSZ 2
#define LSEQ 4097            // 1 + 4*1024
#define DM 256               // D_MODEL
#define DIM 512
#define DIN 512              // D_INNER
#define DST 16               // D_STATE
#define DTR 16               // DT_RANK
#define NROWS (BSZ*LSEQ)     // 8194
#define NCH 65               // ceil(4097/64)
#define CHUNK 64
#define EPSV 1e-5f

// ---------------- scratch (device globals; no runtime alloc) ----------------
__device__ float g_e[2048 * 1024];           // expand GEMM output
__device__ float g_u[NROWS * DM];            // layer ping
__device__ float g_u2[NROWS * DM];           // layer pong
__device__ float g_xz[NROWS * 1024];         // in_proj output (xi | z)
__device__ float g_xc[NROWS * DIN];          // conv+silu output
__device__ float g_dbc[NROWS * 48];          // dt|B|C
__device__ float g_delta[NROWS * DIN];       // softplus(dt@Wdt+b)
__device__ float g_y[NROWS * DIN];           // scan output
__device__ float g_A[DIN * DST];             // -exp(A_log) for current layer
__device__ float g_Ap[BSZ * DIN * DST * NCH];
__device__ float g_Hl[BSZ * DIN * DST * NCH];
__device__ float g_Hi[BSZ * DIN * DST * NCH];
__device__ float g_part[128 * DM];
__device__ float g_partsq[128 * DM];
__device__ float g_mean[DM];
__device__ float g_var[DM];

// ---------------- generic NT SGEMM: C[m,n] = sum_k A[m,k] * W[n,k] ----------------
// A row r lives at A + (r/rpb)*bsa + (r%rpb)*lda  (handles the cls-row skip in x)
// epi: 0 none, 1 +bias, 2 softplus(. + bias)
#define BM 64
#define BN 64
#define BK 16
__global__ void sgemm_nt(const float* __restrict__ A, const float* __restrict__ W,
                         const float* __restrict__ bias, float* __restrict__ C,
                         int M, int N, int K, int lda, int rpb, long long bsa,
                         int ldc, int epi)
{
    __shared__ float As[BM][BK + 1];
    __shared__ float Ws[BN][BK + 1];
    int bm = blockIdx.x * BM, bn = blockIdx.y * BN;
    int tid = threadIdx.x;
    int tx = tid & 15, ty = tid >> 4;
    float acc[4][4] = {};
    for (int k0 = 0; k0 < K; k0 += BK) {
        #pragma unroll
        for (int i = tid; i < BM * BK; i += 256) {
            int m = i >> 4, k = i & 15;
            int r = bm + m;
            float v = 0.f;
            if (r < M)
                v = A[(long long)(r / rpb) * bsa + (long long)(r % rpb) * lda + k0 + k];
            As[m][k] = v;
        }
        #pragma unroll
        for (int i = tid; i < BN * BK; i += 256) {
            int n = i >> 4, k = i & 15;
            int c = bn + n;
            float v = 0.f;
            if (c < N) v = W[(long long)c * K + k0 + k];
            Ws[n][k] = v;
        }
        __syncthreads();
        #pragma unroll
        for (int k = 0; k < BK; k++) {
            float a[4], w[4];
            #pragma unroll
            for (int i = 0; i < 4; i++) a[i] = As[ty * 4 + i][k];
            #pragma unroll
            for (int j = 0; j < 4; j++) w[j] = Ws[tx * 4 + j][k];
            #pragma unroll
            for (int i = 0; i < 4; i++)
                #pragma unroll
                for (int j = 0; j < 4; j++)
                    acc[i][j] += a[i] * w[j];
        }
        __syncthreads();
    }
    #pragma unroll
    for (int i = 0; i < 4; i++) {
        int r = bm + ty * 4 + i;
        if (r >= M) continue;
        #pragma unroll
        for (int j = 0; j < 4; j++) {
            int c = bn + tx * 4 + j;
            if (c >= N) continue;
            float v = acc[i][j];
            if (epi >= 1) v += bias[c];
            if (epi == 2) v = (v > 20.f) ? v : log1pf(expf(v));
            C[(long long)r * ldc + c] = v;
        }
    }
}

// ---------------- cls token: u[b,0,:] = x[b,0,:] @ cls_w^T + cls_b + skip ----------------
__global__ void cls_kernel(const float* __restrict__ x, const float* __restrict__ cls_w,
                           const float* __restrict__ cls_b, const float* __restrict__ skip,
                           float* __restrict__ u)
{
    int b = blockIdx.x;
    int m = threadIdx.x;
    __shared__ float xs[DIM];
    for (int i = m; i < DIM; i += 256) xs[i] = x[(long long)b * 1025 * DIM + i];
    __syncthreads();
    float acc = 0.f;
    #pragma unroll 4
    for (int k = 0; k < DIM; k++) acc += xs[k] * cls_w[m * DIM + k];
    long long row = (long long)b * LSEQ;
    u[row * DM + m] = acc + cls_b[m] + skip[row * DM + m];
}

// ---------------- pixel-shuffle + LayerNorm + skip-add ----------------
__global__ void ln_expand_kernel(const float* __restrict__ e, const float* __restrict__ g,
                                 const float* __restrict__ bb, const float* __restrict__ skip,
                                 float* __restrict__ u)
{
    int o = blockIdx.x;                 // [0, 8192)
    int m = threadIdx.x;                // [0, 256)
    int b = o >> 12, rem = o & 4095;
    int t = rem >> 10, ti = rem & 1023;
    int q = ti & 1, w = (ti >> 1) & 15, p = (ti >> 5) & 1, h = ti >> 6;
    int n = h * 16 + w, pq = p * 2 + q;
    long long erow = (long long)((b * 4 + t) * 256 + n);
    float v = e[erow * 1024 + pq * 256 + m];
    __shared__ float red[8];
    float s = v;
    #pragma unroll
    for (int off = 16; off; off >>= 1) s += __shfl_xor_sync(~0u, s, off);
    if ((m & 31) == 0) red[m >> 5] = s;
    __syncthreads();
    float tot = 0.f;
    #pragma unroll
    for (int i = 0; i < 8; i++) tot += red[i];
    float mu = tot * (1.f / 256.f);
    __syncthreads();
    float dv = v - mu;
    s = dv * dv;
    #pragma unroll
    for (int off = 16; off; off >>= 1) s += __shfl_xor_sync(~0u, s, off);
    if ((m & 31) == 0) red[m >> 5] = s;
    __syncthreads();
    tot = 0.f;
    #pragma unroll
    for (int i = 0; i < 8; i++) tot += red[i];
    float var = tot * (1.f / 256.f);
    long long urow = (long long)b * LSEQ + 1 + t * 1024 + ti;
    u[urow * DM + m] = dv * rsqrtf(var + EPSV) * g[m] + bb[m] + skip[urow * DM + m];
}

// ---------------- depthwise causal conv (k=4) + silu ----------------
__global__ void conv_kernel(const float* __restrict__ xz, const float* __restrict__ cw,
                            const float* __restrict__ cb, float* __restrict__ xc)
{
    long long idx = (long long)blockIdx.x * 256 + threadIdx.x;
    if (idx >= (long long)NROWS * DIN) return;
    int d = (int)(idx & 511);
    long long r = idx >> 9;
    int b = (int)(r / LSEQ);
    int l = (int)(r % LSEQ);
    float acc = cb[d];
    #pragma unroll
    for (int k = 0; k < 4; k++) {
        int ls = l - 3 + k;
        if (ls >= 0) acc += cw[d * 4 + k] * xz[((long long)b * LSEQ + ls) * 1024 + d];
    }
    xc[idx] = acc / (1.f + __expf(-acc));
}

// ---------------- A = -exp(A_log) ----------------
__global__ void negexp_kernel(const float* __restrict__ A_log, float* __restrict__ A)
{
    int i = blockIdx.x * 256 + threadIdx.x;
    if (i < DIN * DST) A[i] = -expf(A_log[i]);
}

// ---------------- chunked scan, pass 1: local scans + decay products ----------------
__global__ void scan1_kernel(const float* __restrict__ delta, const float* __restrict__ xc,
                             const float* __restrict__ dbc, const float* __restrict__ Aneg,
                             float* __restrict__ Aprod, float* __restrict__ Hloc)
{
    int gid = blockIdx.x * 16 + (threadIdx.x >> 4);
    int lane = threadIdx.x & 15;
    int d = gid % DIN;
    int rest = gid / DIN;
    int c = rest % NCH;
    int b = rest / NCH;
    float An = Aneg[d * DST + lane];
    float h = 0.f, ap = 1.f;
    int l0 = c * CHUNK;
    int lend = min(l0 + CHUNK, LSEQ);
    for (int l = l0; l < lend; l++) {
        long long row = (long long)b * LSEQ + l;
        float dl = delta[row * DIN + d];
        float xv = xc[row * DIN + d];
        float Bv = dbc[row * 48 + 16 + lane];
        float a = __expf(dl * An);
        h = h * a + dl * Bv * xv;
        ap *= a;
    }
    long long base = (((long long)b * DIN + d) * DST + lane) * NCH + c;
    Aprod[base] = ap;
    Hloc[base] = h;
}

// ---------------- pass 2: inter-chunk exclusive scan (65 steps, 16384 series) ----------------
__global__ void scan2_kernel(const float* __restrict__ Aprod, const float* __restrict__ Hloc,
                             float* __restrict__ Hinit)
{
    int i = blockIdx.x * 256 + threadIdx.x;
    if (i >= BSZ * DIN * DST) return;
    long long base = (long long)i * NCH;
    float h = 0.f;
    for (int c = 0; c < NCH; c++) {
        Hinit[base + c] = h;
        h = h * Aprod[base + c] + Hloc[base + c];
    }
}

// ---------------- pass 3: replay with true init state, fuse y = (h.C + x*D)*silu(z) ----------------
__global__ void scan3_kernel(const float* __restrict__ delta, const float* __restrict__ xc,
                             const float* __restrict__ dbc, const float* __restrict__ Aneg,
                             const float* __restrict__ Hinit, const float* __restrict__ xz,
                             const float* __restrict__ Dp, float* __restrict__ y)
{
    int gid = blockIdx.x * 16 + (threadIdx.x >> 4);
    int lane = threadIdx.x & 15;
    int d = gid % DIN;
    int rest = gid / DIN;
    int c = rest % NCH;
    int b = rest / NCH;
    float An = Aneg[d * DST + lane];
    float Dd = Dp[d];
    long long base = (((long long)b * DIN + d) * DST + lane) * NCH + c;
    float h = Hinit[base];
    int l0 = c * CHUNK;
    int lend = min(l0 + CHUNK, LSEQ);
    for (int l = l0; l < lend; l++) {
        long long row = (long long)b * LSEQ + l;
        float dl = delta[row * DIN + d];
        float xv = xc[row * DIN + d];
        float Bv = dbc[row * 48 + 16 + lane];
        float Cv = dbc[row * 48 + 32 + lane];
        float a = __expf(dl * An);
        h = h * a + dl * Bv * xv;
        float py = h * Cv;
        py += __shfl_xor_sync(~0u, py, 8, 16);
        py += __shfl_xor_sync(~0u, py, 4, 16);
        py += __shfl_xor_sync(~0u, py, 2, 16);
        py += __shfl_xor_sync(~0u, py, 1, 16);
        if (lane == 0) {
            float z = xz[row * 1024 + 512 + d];
            float sz = z / (1.f + __expf(-z));
            y[row * DIN + d] = (py + xv * Dd) * sz;
        }
    }
}

// ---------------- deterministic batchnorm ----------------
__global__ void bn_part_kernel(const float* __restrict__ u, float* __restrict__ part,
                               float* __restrict__ partsq)
{
    int blk = blockIdx.x;       // 128 blocks
    int m = threadIdx.x;        // channel
    int r0 = blk * 65;
    int r1 = min(r0 + 65, NROWS);
    float s = 0.f, q = 0.f;
    for (int r = r0; r < r1; r++) {
        float v = u[(long long)r * DM + m];
        s += v; q += v * v;
    }
    part[blk * DM + m] = s;
    partsq[blk * DM + m] = q;
}

__global__ void bn_final_kernel(const float* __restrict__ part, const float* __restrict__ partsq,
                                float* __restrict__ mean, float* __restrict__ var)
{
    int m = threadIdx.x;
    float s = 0.f, q = 0.f;
    for (int i = 0; i < 128; i++) { s += part[i * DM + m]; q += partsq[i * DM + m]; }
    float mu = s / (float)NROWS;
    mean[m] = mu;
    var[m] = q / (float)NROWS - mu * mu;
}

__global__ void bn_norm_kernel(const float* __restrict__ u, const float* __restrict__ mean,
                               const float* __restrict__ var, const float* __restrict__ g,
                               const float* __restrict__ bb, float* __restrict__ out,
                               long long out_size)
{
    long long idx = (long long)blockIdx.x * 256 + threadIdx.x;
    if (idx >= out_size) return;
    const long long NEL = (long long)NROWS * DM;
    if (idx < NEL) {
        int m = (int)(idx & 255);
        out[idx] = (u[idx] - mean[m]) * rsqrtf(var[m] + EPSV) * g[m] + bb[m];
    } else {
        out[idx] = 1024.0f;   // second tuple element: 4*N
    }
}

// ---------------- launch ----------------
extern "C" void kernel_launch(void* const* d_in, const int* in_sizes, int n_in,
                              void* d_out, int out_size)
{
    const float* x        = (const float*)d_in[0];
    const float* skip     = (const float*)d_in[1];
    const float* exp_w    = (const float*)d_in[2];
    const float* ln_g     = (const float*)d_in[3];
    const float* ln_b     = (const float*)d_in[4];
    const float* cls_w    = (const float*)d_in[5];
    const float* cls_b    = (const float*)d_in[6];
    const float* in_proj_w= (const float*)d_in[7];
    const float* conv_w   = (const float*)d_in[8];
    const float* conv_b   = (const float*)d_in[9];
    const float* xproj_w  = (const float*)d_in[10];
    const float* dt_w     = (const float*)d_in[11];
    const float* dt_b     = (const float*)d_in[12];
    const float* A_log    = (const float*)d_in[13];
    const float* Dp       = (const float*)d_in[14];
    const float* out_w    = (const float*)d_in[15];
    const float* bn_g     = (const float*)d_in[16];
    const float* bn_b     = (const float*)d_in[17];
    float* out = (float*)d_out;

    float *pe, *pu, *pu2, *pxz, *pxc, *pdbc, *pdelta, *py, *pA, *pAp, *pHl, *pHi;
    float *ppart, *ppartsq, *pmean, *pvar;
    cudaGetSymbolAddress((void**)&pe, g_e);
    cudaGetSymbolAddress((void**)&pu, g_u);
    cudaGetSymbolAddress((void**)&pu2, g_u2);
    cudaGetSymbolAddress((void**)&pxz, g_xz);
    cudaGetSymbolAddress((void**)&pxc, g_xc);
    cudaGetSymbolAddress((void**)&pdbc, g_dbc);
    cudaGetSymbolAddress((void**)&pdelta, g_delta);
    cudaGetSymbolAddress((void**)&py, g_y);
    cudaGetSymbolAddress((void**)&pA, g_A);
    cudaGetSymbolAddress((void**)&pAp, g_Ap);
    cudaGetSymbolAddress((void**)&pHl, g_Hl);
    cudaGetSymbolAddress((void**)&pHi, g_Hi);
    cudaGetSymbolAddress((void**)&ppart, g_part);
    cudaGetSymbolAddress((void**)&ppartsq, g_partsq);
    cudaGetSymbolAddress((void**)&pmean, g_mean);
    cudaGetSymbolAddress((void**)&pvar, g_var);

    // 1. cls token rows
    cls_kernel<<<2, 256>>>(x, cls_w, cls_b, skip, pu);

    // 2. expand GEMM: (2048 tokens, 512) x (1024, 512)^T  -> g_e
    //    A rows skip the cls row of each batch: base x+512, batch stride 1025*512
    sgemm_nt<<<dim3(32, 16), 256>>>(x + 512, exp_w, nullptr, pe,
                                    2048, 1024, 512, 512, 1024, (long long)1025 * 512, 1024, 0);

    // 3. pixel-shuffle + LN + skip
    ln_expand_kernel<<<8192, 256>>>(pe, ln_g, ln_b, skip, pu);

    float* uin = pu;
    float* uout = pu2;
    const int HUGE_RPB = 1 << 30;
    for (int layer = 0; layer < 2; layer++) {
        negexp_kernel<<<32, 256>>>(A_log + (size_t)layer * DIN * DST, pA);
        // in_proj: (8194,256) x (1024,256)^T -> xz
        sgemm_nt<<<dim3(129, 16), 256>>>(uin, in_proj_w + (size_t)layer * 1024 * DM, nullptr, pxz,
                                         NROWS, 1024, DM, DM, HUGE_RPB, 0, 1024, 0);
        // depthwise conv + silu
        conv_kernel<<<16388, 256>>>(pxz, conv_w + (size_t)layer * DIN * 4,
                                    conv_b + (size_t)layer * DIN, pxc);
        // x_proj: (8194,512) x (48,512)^T -> dbc
        sgemm_nt<<<dim3(129, 1), 256>>>(pxc, xproj_w + (size_t)layer * 48 * DIN, nullptr, pdbc,
                                        NROWS, 48, DIN, DIN, HUGE_RPB, 0, 48, 0);
        // delta: softplus(dt @ Wdt^T + bdt): (8194,16) x (512,16)^T
        sgemm_nt<<<dim3(129, 8), 256>>>(pdbc, dt_w + (size_t)layer * DIN * DTR,
                                        dt_b + (size_t)layer * DIN, pdelta,
                                        NROWS, DIN, DTR, 48, HUGE_RPB, 0, DIN, 2);
        // chunked selective scan
        scan1_kernel<<<4160, 256>>>(pdelta, pxc, pdbc, pA, pAp, pHl);
        scan2_kernel<<<64, 256>>>(pAp, pHl, pHi);
        scan3_kernel<<<4160, 256>>>(pdelta, pxc, pdbc, pA, pHi, pxz,
                                    Dp + (size_t)layer * DIN, py);
        // out_proj: (8194,512) x (256,512)^T -> uout
        sgemm_nt<<<dim3(129, 4), 256>>>(py, out_w + (size_t)layer * DM * DIN, nullptr, uout,
                                        NROWS, DM, DIN, DIN, HUGE_RPB, 0, DM, 0);
        float* tmp = uin; uin = uout; uout = tmp;
    }

    // batchnorm (deterministic two-stage reduction)
    bn_part_kernel<<<128, 256>>>(uin, ppart, ppartsq);
    bn_final_kernel<<<1, 256>>>(ppart, ppartsq, pmean, pvar);
    long long nb = ((long long)out_size + 255) / 256;
    bn_norm_kernel<<<(int)nb, 256>>>(uin, pmean, pvar, bn_g, bn_b, out, (long long)out_size);
}

// round 3
// speedup vs baseline: 1.5076x; 1.5076x over previous
#include <cuda_runtime.h>
#include <cuda_bf16.h>

// ---------------- constants ----------------
#define BSZ 2
#define LSEQ 4097            // 1 + 4*1024
#define DM 256               // D_MODEL
#define DIM 512
#define DIN 512              // D_INNER
#define DST 16               // D_STATE
#define DTR 16               // DT_RANK
#define NROWS (BSZ*LSEQ)     // 8194
#define NCH 65               // ceil(4097/64)
#define CHUNK 64
#define EPSV 1e-5f

// ---------------- scratch (device globals; no runtime alloc) ----------------
__device__ __align__(16) float g_e[2048 * 1024];           // expand GEMM output
__device__ __align__(16) float g_u[NROWS * DM];            // layer ping
__device__ __align__(16) float g_u2[NROWS * DM];           // layer pong
__device__ __align__(16) float g_xz[NROWS * 1024];         // in_proj output (xi | z)
__device__ __align__(16) float g_xc[NROWS * DIN];          // conv+silu output
__device__ __align__(16) float g_dbc[NROWS * 48];          // dt|B|C
__device__ __align__(16) float g_delta[NROWS * DIN];       // softplus(dt@Wdt+b)
__device__ __align__(16) float g_y[NROWS * DIN];           // scan output
__device__ __align__(16) float g_A[DIN * DST];             // -exp(A_log) for current layer
__device__ __align__(16) float g_Ap[BSZ * DIN * DST * NCH];
__device__ __align__(16) float g_Hl[BSZ * DIN * DST * NCH];
__device__ __align__(16) float g_Hi[BSZ * DIN * DST * NCH];
__device__ __align__(16) float g_part[128 * DM];
__device__ __align__(16) float g_partsq[128 * DM];
__device__ __align__(16) float g_mean[DM];
__device__ __align__(16) float g_var[DM];

// ---------------- high-throughput NT SGEMM: C[m,n] = sum_k A[m,k] * W[n,k] ----------------
// 128x64 block tile, BK=16, 8x4 microtile, k-major smem, single buffer with
// register prefetch of the next global tile (unconditional syncs only).
// A row r lives at A + (r/rpb)*bsa + (r%rpb)*lda  (handles the cls-row skip in x)
// epi: 0 none, 1 +bias, 2 softplus(. + bias).  Requires K % 16 == 0, lda % 4 == 0.
#define BM 128
#define BN 64
#define BK 16
__global__ __launch_bounds__(256) void sgemm_nt(
    const float* __restrict__ A, const float* __restrict__ W,
    const float* __restrict__ bias, float* __restrict__ C,
    int M, int N, int K, int lda, int rpb, long long bsa,
    int ldc, int epi)
{
    __shared__ __align__(16) float As[BK][BM + 4];
    __shared__ __align__(16) float Ws[BK][BN + 4];
    const int tid = threadIdx.x;
    const int bm = blockIdx.x * BM, bn = blockIdx.y * BN;

    // global-load assignments (fixed per thread)
    const int am0 = tid >> 2;            // 0..63
    const int am1 = am0 + 64;            // 64..127
    const int akq = (tid & 3) * 4;       // k offset within BK
    long long arow0 = -1, arow1 = -1;
    {
        int r0 = bm + am0;
        if (r0 < M) arow0 = (long long)(r0 / rpb) * bsa + (long long)(r0 % rpb) * lda;
        int r1 = bm + am1;
        if (r1 < M) arow1 = (long long)(r1 / rpb) * bsa + (long long)(r1 % rpb) * lda;
    }
    const int wn = tid >> 2;             // 0..63
    const int wkq = (tid & 3) * 4;
    long long wrow = -1;
    if (bn + wn < N) wrow = (long long)(bn + wn) * K;

    const float4 z4 = make_float4(0.f, 0.f, 0.f, 0.f);
    float4 fa0, fa1, fw;

    // prefetch tile 0 into registers
    fa0 = (arow0 >= 0) ? __ldg((const float4*)(A + arow0 + akq)) : z4;
    fa1 = (arow1 >= 0) ? __ldg((const float4*)(A + arow1 + akq)) : z4;
    fw  = (wrow  >= 0) ? __ldg((const float4*)(W + wrow + wkq))  : z4;

    const int ty = tid >> 4, tx = tid & 15;
    const int m0 = ty * 8, n0 = tx * 4;
    float acc[8][4] = {};
    const int nk = K / BK;

    for (int t = 0; t < nk; t++) {
        __syncthreads();   // everyone done reading smem from previous tile
        As[akq + 0][am0] = fa0.x; As[akq + 1][am0] = fa0.y;
        As[akq + 2][am0] = fa0.z; As[akq + 3][am0] = fa0.w;
        As[akq + 0][am1] = fa1.x; As[akq + 1][am1] = fa1.y;
        As[akq + 2][am1] = fa1.z; As[akq + 3][am1] = fa1.w;
        Ws[wkq + 0][wn]  = fw.x;  Ws[wkq + 1][wn]  = fw.y;
        Ws[wkq + 2][wn]  = fw.z;  Ws[wkq + 3][wn]  = fw.w;
        __syncthreads();

        if (t + 1 < nk) {   // prefetch next tile into registers (overlaps compute)
            const int k0 = (t + 1) * BK;
            fa0 = (arow0 >= 0) ? __ldg((const float4*)(A + arow0 + k0 + akq)) : z4;
            fa1 = (arow1 >= 0) ? __ldg((const float4*)(A + arow1 + k0 + akq)) : z4;
            fw  = (wrow  >= 0) ? __ldg((const float4*)(W + wrow + k0 + wkq))  : z4;
        }

        #pragma unroll
        for (int k = 0; k < BK; k++) {
            float4 a0 = *(const float4*)&As[k][m0];
            float4 a1 = *(const float4*)&As[k][m0 + 4];
            float4 w  = *(const float4*)&Ws[k][n0];
            float av[8] = {a0.x, a0.y, a0.z, a0.w, a1.x, a1.y, a1.z, a1.w};
            float wv[4] = {w.x, w.y, w.z, w.w};
            #pragma unroll
            for (int i = 0; i < 8; i++)
                #pragma unroll
                for (int j = 0; j < 4; j++)
                    acc[i][j] += av[i] * wv[j];
        }
    }

    // epilogue
    #pragma unroll
    for (int i = 0; i < 8; i++) {
        int r = bm + m0 + i;
        if (r >= M) continue;
        float v[4];
        #pragma unroll
        for (int j = 0; j < 4; j++) {
            v[j] = acc[i][j];
            int c = bn + n0 + j;
            if (c < N && epi >= 1) v[j] += bias[c];
            if (epi == 2) v[j] = (v[j] > 20.f) ? v[j] : log1pf(expf(v[j]));
        }
        long long base = (long long)r * ldc + bn + n0;
        if (bn + n0 + 3 < N) {
            *(float4*)&C[base] = make_float4(v[0], v[1], v[2], v[3]);
        } else {
            #pragma unroll
            for (int j = 0; j < 4; j++)
                if (bn + n0 + j < N) C[base + j] = v[j];
        }
    }
}

// ---------------- cls token: u[b,0,:] = x[b,0,:] @ cls_w^T + cls_b + skip ----------------
__global__ void cls_kernel(const float* __restrict__ x, const float* __restrict__ cls_w,
                           const float* __restrict__ cls_b, const float* __restrict__ skip,
                           float* __restrict__ u)
{
    int b = blockIdx.x;
    int m = threadIdx.x;
    __shared__ float xs[DIM];
    for (int i = m; i < DIM; i += 256) xs[i] = x[(long long)b * 1025 * DIM + i];
    __syncthreads();
    float acc = 0.f;
    #pragma unroll 4
    for (int k = 0; k < DIM; k++) acc += xs[k] * cls_w[m * DIM + k];
    long long row = (long long)b * LSEQ;
    u[row * DM + m] = acc + cls_b[m] + skip[row * DM + m];
}

// ---------------- pixel-shuffle + LayerNorm + skip-add ----------------
__global__ void ln_expand_kernel(const float* __restrict__ e, const float* __restrict__ g,
                                 const float* __restrict__ bb, const float* __restrict__ skip,
                                 float* __restrict__ u)
{
    int o = blockIdx.x;                 // [0, 8192)
    int m = threadIdx.x;                // [0, 256)
    int b = o >> 12, rem = o & 4095;
    int t = rem >> 10, ti = rem & 1023;
    int q = ti & 1, w = (ti >> 1) & 15, p = (ti >> 5) & 1, h = ti >> 6;
    int n = h * 16 + w, pq = p * 2 + q;
    long long erow = (long long)((b * 4 + t) * 256 + n);
    float v = e[erow * 1024 + pq * 256 + m];
    __shared__ float red[8];
    float s = v;
    #pragma unroll
    for (int off = 16; off; off >>= 1) s += __shfl_xor_sync(~0u, s, off);
    if ((m & 31) == 0) red[m >> 5] = s;
    __syncthreads();
    float tot = 0.f;
    #pragma unroll
    for (int i = 0; i < 8; i++) tot += red[i];
    float mu = tot * (1.f / 256.f);
    __syncthreads();
    float dv = v - mu;
    s = dv * dv;
    #pragma unroll
    for (int off = 16; off; off >>= 1) s += __shfl_xor_sync(~0u, s, off);
    if ((m & 31) == 0) red[m >> 5] = s;
    __syncthreads();
    tot = 0.f;
    #pragma unroll
    for (int i = 0; i < 8; i++) tot += red[i];
    float var = tot * (1.f / 256.f);
    long long urow = (long long)b * LSEQ + 1 + t * 1024 + ti;
    u[urow * DM + m] = dv * rsqrtf(var + EPSV) * g[m] + bb[m] + skip[urow * DM + m];
}

// ---------------- depthwise causal conv (k=4) + silu ----------------
__global__ void conv_kernel(const float* __restrict__ xz, const float* __restrict__ cw,
                            const float* __restrict__ cb, float* __restrict__ xc)
{
    long long idx = (long long)blockIdx.x * 256 + threadIdx.x;
    if (idx >= (long long)NROWS * DIN) return;
    int d = (int)(idx & 511);
    long long r = idx >> 9;
    int b = (int)(r / LSEQ);
    int l = (int)(r % LSEQ);
    float acc = cb[d];
    #pragma unroll
    for (int k = 0; k < 4; k++) {
        int ls = l - 3 + k;
        if (ls >= 0) acc += cw[d * 4 + k] * xz[((long long)b * LSEQ + ls) * 1024 + d];
    }
    xc[idx] = acc / (1.f + __expf(-acc));
}

// ---------------- A = -exp(A_log) ----------------
__global__ void negexp_kernel(const float* __restrict__ A_log, float* __restrict__ A)
{
    int i = blockIdx.x * 256 + threadIdx.x;
    if (i < DIN * DST) A[i] = -expf(A_log[i]);
}

// ---------------- chunked scan, pass 1: local scans + decay products ----------------
__global__ void scan1_kernel(const float* __restrict__ delta, const float* __restrict__ xc,
                             const float* __restrict__ dbc, const float* __restrict__ Aneg,
                             float* __restrict__ Aprod, float* __restrict__ Hloc)
{
    int gid = blockIdx.x * 16 + (threadIdx.x >> 4);
    int lane = threadIdx.x & 15;
    int d = gid % DIN;
    int rest = gid / DIN;
    int c = rest % NCH;
    int b = rest / NCH;
    float An = Aneg[d * DST + lane];
    float h = 0.f, ap = 1.f;
    int l0 = c * CHUNK;
    int lend = min(l0 + CHUNK, LSEQ);
    for (int l = l0; l < lend; l++) {
        long long row = (long long)b * LSEQ + l;
        float dl = delta[row * DIN + d];
        float xv = xc[row * DIN + d];
        float Bv = dbc[row * 48 + 16 + lane];
        float a = __expf(dl * An);
        h = h * a + dl * Bv * xv;
        ap *= a;
    }
    long long base = (((long long)b * DIN + d) * DST + lane) * NCH + c;
    Aprod[base] = ap;
    Hloc[base] = h;
}

// ---------------- pass 2: inter-chunk exclusive scan (65 steps, 16384 series) ----------------
__global__ void scan2_kernel(const float* __restrict__ Aprod, const float* __restrict__ Hloc,
                             float* __restrict__ Hinit)
{
    int i = blockIdx.x * 256 + threadIdx.x;
    if (i >= BSZ * DIN * DST) return;
    long long base = (long long)i * NCH;
    float h = 0.f;
    for (int c = 0; c < NCH; c++) {
        Hinit[base + c] = h;
        h = h * Aprod[base + c] + Hloc[base + c];
    }
}

// ---------------- pass 3: replay with true init state, fuse y = (h.C + x*D)*silu(z) ----------------
__global__ void scan3_kernel(const float* __restrict__ delta, const float* __restrict__ xc,
                             const float* __restrict__ dbc, const float* __restrict__ Aneg,
                             const float* __restrict__ Hinit, const float* __restrict__ xz,
                             const float* __restrict__ Dp, float* __restrict__ y)
{
    int gid = blockIdx.x * 16 + (threadIdx.x >> 4);
    int lane = threadIdx.x & 15;
    int d = gid % DIN;
    int rest = gid / DIN;
    int c = rest % NCH;
    int b = rest / NCH;
    float An = Aneg[d * DST + lane];
    float Dd = Dp[d];
    long long base = (((long long)b * DIN + d) * DST + lane) * NCH + c;
    float h = Hinit[base];
    int l0 = c * CHUNK;
    int lend = min(l0 + CHUNK, LSEQ);
    for (int l = l0; l < lend; l++) {
        long long row = (long long)b * LSEQ + l;
        float dl = delta[row * DIN + d];
        float xv = xc[row * DIN + d];
        float Bv = dbc[row * 48 + 16 + lane];
        float Cv = dbc[row * 48 + 32 + lane];
        float a = __expf(dl * An);
        h = h * a + dl * Bv * xv;
        float py = h * Cv;
        py += __shfl_xor_sync(~0u, py, 8, 16);
        py += __shfl_xor_sync(~0u, py, 4, 16);
        py += __shfl_xor_sync(~0u, py, 2, 16);
        py += __shfl_xor_sync(~0u, py, 1, 16);
        if (lane == 0) {
            float z = xz[row * 1024 + 512 + d];
            float sz = z / (1.f + __expf(-z));
            y[row * DIN + d] = (py + xv * Dd) * sz;
        }
    }
}

// ---------------- deterministic batchnorm ----------------
__global__ void bn_part_kernel(const float* __restrict__ u, float* __restrict__ part,
                               float* __restrict__ partsq)
{
    int blk = blockIdx.x;       // 128 blocks
    int m = threadIdx.x;        // channel
    int r0 = blk * 65;
    int r1 = min(r0 + 65, NROWS);
    float s = 0.f, q = 0.f;
    for (int r = r0; r < r1; r++) {
        float v = u[(long long)r * DM + m];
        s += v; q += v * v;
    }
    part[blk * DM + m] = s;
    partsq[blk * DM + m] = q;
}

__global__ void bn_final_kernel(const float* __restrict__ part, const float* __restrict__ partsq,
                                float* __restrict__ mean, float* __restrict__ var)
{
    int m = threadIdx.x;
    float s = 0.f, q = 0.f;
    for (int i = 0; i < 128; i++) { s += part[i * DM + m]; q += partsq[i * DM + m]; }
    float mu = s / (float)NROWS;
    mean[m] = mu;
    var[m] = q / (float)NROWS - mu * mu;
}

__global__ void bn_norm_kernel(const float* __restrict__ u, const float* __restrict__ mean,
                               const float* __restrict__ var, const float* __restrict__ g,
                               const float* __restrict__ bb, float* __restrict__ out,
                               long long out_size)
{
    long long idx = (long long)blockIdx.x * 256 + threadIdx.x;
    if (idx >= out_size) return;
    const long long NEL = (long long)NROWS * DM;
    if (idx < NEL) {
        int m = (int)(idx & 255);
        out[idx] = (u[idx] - mean[m]) * rsqrtf(var[m] + EPSV) * g[m] + bb[m];
    } else {
        out[idx] = 1024.0f;   // second tuple element: 4*N
    }
}

// ---------------- launch ----------------
extern "C" void kernel_launch(void* const* d_in, const int* in_sizes, int n_in,
                              void* d_out, int out_size)
{
    const float* x        = (const float*)d_in[0];
    const float* skip     = (const float*)d_in[1];
    const float* exp_w    = (const float*)d_in[2];
    const float* ln_g     = (const float*)d_in[3];
    const float* ln_b     = (const float*)d_in[4];
    const float* cls_w    = (const float*)d_in[5];
    const float* cls_b    = (const float*)d_in[6];
    const float* in_proj_w= (const float*)d_in[7];
    const float* conv_w   = (const float*)d_in[8];
    const float* conv_b   = (const float*)d_in[9];
    const float* xproj_w  = (const float*)d_in[10];
    const float* dt_w     = (const float*)d_in[11];
    const float* dt_b     = (const float*)d_in[12];
    const float* A_log    = (const float*)d_in[13];
    const float* Dp       = (const float*)d_in[14];
    const float* out_w    = (const float*)d_in[15];
    const float* bn_g     = (const float*)d_in[16];
    const float* bn_b     = (const float*)d_in[17];
    float* out = (float*)d_out;

    float *pe, *pu, *pu2, *pxz, *pxc, *pdbc, *pdelta, *py, *pA, *pAp, *pHl, *pHi;
    float *ppart, *ppartsq, *pmean, *pvar;
    cudaGetSymbolAddress((void**)&pe, g_e);
    cudaGetSymbolAddress((void**)&pu, g_u);
    cudaGetSymbolAddress((void**)&pu2, g_u2);
    cudaGetSymbolAddress((void**)&pxz, g_xz);
    cudaGetSymbolAddress((void**)&pxc, g_xc);
    cudaGetSymbolAddress((void**)&pdbc, g_dbc);
    cudaGetSymbolAddress((void**)&pdelta, g_delta);
    cudaGetSymbolAddress((void**)&py, g_y);
    cudaGetSymbolAddress((void**)&pA, g_A);
    cudaGetSymbolAddress((void**)&pAp, g_Ap);
    cudaGetSymbolAddress((void**)&pHl, g_Hl);
    cudaGetSymbolAddress((void**)&pHi, g_Hi);
    cudaGetSymbolAddress((void**)&ppart, g_part);
    cudaGetSymbolAddress((void**)&ppartsq, g_partsq);
    cudaGetSymbolAddress((void**)&pmean, g_mean);
    cudaGetSymbolAddress((void**)&pvar, g_var);

    // 1. cls token rows
    cls_kernel<<<2, 256>>>(x, cls_w, cls_b, skip, pu);

    // 2. expand GEMM: (2048 tokens, 512) x (1024, 512)^T  -> g_e
    sgemm_nt<<<dim3(16, 16), 256>>>(x + 512, exp_w, nullptr, pe,
                                    2048, 1024, 512, 512, 1024, (long long)1025 * 512, 1024, 0);

    // 3. pixel-shuffle + LN + skip
    ln_expand_kernel<<<8192, 256>>>(pe, ln_g, ln_b, skip, pu);

    float* uin = pu;
    float* uout = pu2;
    const int HUGE_RPB = 1 << 30;
    for (int layer = 0; layer < 2; layer++) {
        negexp_kernel<<<32, 256>>>(A_log + (size_t)layer * DIN * DST, pA);
        // in_proj: (8194,256) x (1024,256)^T -> xz
        sgemm_nt<<<dim3(65, 16), 256>>>(uin, in_proj_w + (size_t)layer * 1024 * DM, nullptr, pxz,
                                        NROWS, 1024, DM, DM, HUGE_RPB, 0, 1024, 0);
        // depthwise conv + silu
        conv_kernel<<<16388, 256>>>(pxz, conv_w + (size_t)layer * DIN * 4,
                                    conv_b + (size_t)layer * DIN, pxc);
        // x_proj: (8194,512) x (48,512)^T -> dbc
        sgemm_nt<<<dim3(65, 1), 256>>>(pxc, xproj_w + (size_t)layer * 48 * DIN, nullptr, pdbc,
                                       NROWS, 48, DIN, DIN, HUGE_RPB, 0, 48, 0);
        // delta: softplus(dt @ Wdt^T + bdt): (8194,16) x (512,16)^T
        sgemm_nt<<<dim3(65, 8), 256>>>(pdbc, dt_w + (size_t)layer * DIN * DTR,
                                       dt_b + (size_t)layer * DIN, pdelta,
                                       NROWS, DIN, DTR, 48, HUGE_RPB, 0, DIN, 2);
        // chunked selective scan
        scan1_kernel<<<4160, 256>>>(pdelta, pxc, pdbc, pA, pAp, pHl);
        scan2_kernel<<<64, 256>>>(pAp, pHl, pHi);
        scan3_kernel<<<4160, 256>>>(pdelta, pxc, pdbc, pA, pHi, pxz,
                                    Dp + (size_t)layer * DIN, py);
        // out_proj: (8194,512) x (256,512)^T -> uout
        sgemm_nt<<<dim3(65, 4), 256>>>(py, out_w + (size_t)layer * DM * DIN, nullptr, uout,
                                       NROWS, DM, DIN, DIN, HUGE_RPB, 0, DM, 0);
        float* tmp = uin; uin = uout; uout = tmp;
    }

    // batchnorm (deterministic two-stage reduction)
    bn_part_kernel<<<128, 256>>>(uin, ppart, ppartsq);
    bn_final_kernel<<<1, 256>>>(ppart, ppartsq, pmean, pvar);
    long long nb = ((long long)out_size + 255) / 256;
    bn_norm_kernel<<<(int)nb, 256>>>(uin, pmean, pvar, bn_g, bn_b, out, (long long)out_size);
}

// round 5
// speedup vs baseline: 1.8095x; 1.2002x over previous
#include <cuda_runtime.h>
#include <cuda_bf16.h>
#include <cstdint>

// ---------------- constants ----------------
#define BSZ 2
#define LSEQ 4097            // 1 + 4*1024
#define DM 256               // D_MODEL
#define DIM 512
#define DIN 512              // D_INNER
#define DST 16               // D_STATE
#define DTR 16               // DT_RANK
#define NROWS (BSZ*LSEQ)     // 8194
#define NCH 65               // ceil(4097/64)
#define CHUNK 64
#define EPSV 1e-5f

// ---------------- scratch (device globals; no runtime alloc) ----------------
__device__ __align__(16) float g_e[2048 * 1024];           // expand GEMM output
__device__ __align__(16) float g_u[NROWS * DM];            // layer ping
__device__ __align__(16) float g_u2[NROWS * DM];           // layer pong
__device__ __align__(16) float g_xz[NROWS * 1024];         // in_proj output (xi | z)
__device__ __align__(16) float g_xc[NROWS * DIN];          // conv+silu output
__device__ __align__(16) float g_dbc[NROWS * 48];          // dt|B|C
__device__ __align__(16) float g_delta[NROWS * DIN];       // softplus(dt@Wdt+b)
__device__ __align__(16) float g_y[NROWS * DIN];           // scan output
__device__ __align__(16) float g_Ap[BSZ * DIN * DST * NCH];
__device__ __align__(16) float g_Hl[BSZ * DIN * DST * NCH];
__device__ __align__(16) float g_Hi[BSZ * DIN * DST * NCH];
__device__ __align__(16) float g_part[128 * DM];
__device__ __align__(16) float g_partsq[128 * DM];
__device__ __align__(16) float g_mean[DM];
__device__ __align__(16) float g_var[DM];

// ---------------- tf32 helpers ----------------
__device__ __forceinline__ uint32_t f2tf32(float x) {
    uint32_t r;
    asm("cvt.rna.tf32.f32 %0, %1;" : "=r"(r) : "f"(x));
    return r;
}

__device__ __forceinline__ void mma_tf32(float c[4],
    uint32_t a0, uint32_t a1, uint32_t a2, uint32_t a3,
    uint32_t b0, uint32_t b1)
{
    asm volatile(
        "mma.sync.aligned.m16n8k8.row.col.f32.tf32.tf32.f32 "
        "{%0,%1,%2,%3}, {%4,%5,%6,%7}, {%8,%9}, {%0,%1,%2,%3};"
        : "+f"(c[0]), "+f"(c[1]), "+f"(c[2]), "+f"(c[3])
        : "r"(a0), "r"(a1), "r"(a2), "r"(a3), "r"(b0), "r"(b1));
}

// ---------------- tensor-core tf32 NT GEMM: C[m,n] = sum_k A[m,k]*W[n,k] ----------------
// 128x64 block tile, BK=16, 8 warps in 4(m) x 2(n), warp tile 32x32 via 2x4 m16n8k8 mma.
// A row r at A + (r/rpb)*bsa + (r%rpb)*lda.  epi: 0 none, 1 +bias, 2 softplus(.+bias).
// Requires K % 16 == 0, lda % 4 == 0.
#define TBM 128
#define TBN 64
#define TBK 16
__global__ __launch_bounds__(256) void tc_gemm(
    const float* __restrict__ A, const float* __restrict__ W,
    const float* __restrict__ bias, float* __restrict__ C,
    int M, int N, int K, int lda, int rpb, long long bsa,
    int ldc, int epi)
{
    __shared__ __align__(16) uint32_t As[TBM][TBK + 4];   // pad row to 20 words
    __shared__ __align__(16) uint32_t Ws[TBN][TBK + 4];
    const int tid = threadIdx.x;
    const int bm = blockIdx.x * TBM, bn = blockIdx.y * TBN;

    // global-load assignments
    const int am0 = tid >> 2;            // 0..63
    const int am1 = am0 + 64;            // 64..127
    const int akq = (tid & 3) * 4;
    long long arow0 = -1, arow1 = -1;
    {
        int r0 = bm + am0;
        if (r0 < M) arow0 = (long long)(r0 / rpb) * bsa + (long long)(r0 % rpb) * lda;
        int r1 = bm + am1;
        if (r1 < M) arow1 = (long long)(r1 / rpb) * bsa + (long long)(r1 % rpb) * lda;
    }
    const int wn = tid >> 2;             // 0..63
    const int wkq = (tid & 3) * 4;
    long long wrow = -1;
    if (bn + wn < N) wrow = (long long)(bn + wn) * K;

    const float4 z4 = make_float4(0.f, 0.f, 0.f, 0.f);
    float4 fa0, fa1, fw;
    fa0 = (arow0 >= 0) ? __ldg((const float4*)(A + arow0 + akq)) : z4;
    fa1 = (arow1 >= 0) ? __ldg((const float4*)(A + arow1 + akq)) : z4;
    fw  = (wrow  >= 0) ? __ldg((const float4*)(W + wrow + wkq))  : z4;

    const int wid = tid >> 5, lane = tid & 31;
    const int wm  = (wid & 3) * 32;      // warp m origin in tile
    const int wnn = (wid >> 2) * 32;     // warp n origin in tile
    const int gid = lane >> 2, tig = lane & 3;

    float acc[2][4][4];
    #pragma unroll
    for (int mt = 0; mt < 2; mt++)
        #pragma unroll
        for (int nt = 0; nt < 4; nt++)
            #pragma unroll
            for (int i = 0; i < 4; i++) acc[mt][nt][i] = 0.f;

    const int nk = K / TBK;
    for (int t = 0; t < nk; t++) {
        __syncthreads();
        As[am0][akq + 0] = f2tf32(fa0.x); As[am0][akq + 1] = f2tf32(fa0.y);
        As[am0][akq + 2] = f2tf32(fa0.z); As[am0][akq + 3] = f2tf32(fa0.w);
        As[am1][akq + 0] = f2tf32(fa1.x); As[am1][akq + 1] = f2tf32(fa1.y);
        As[am1][akq + 2] = f2tf32(fa1.z); As[am1][akq + 3] = f2tf32(fa1.w);
        Ws[wn][wkq + 0]  = f2tf32(fw.x);  Ws[wn][wkq + 1]  = f2tf32(fw.y);
        Ws[wn][wkq + 2]  = f2tf32(fw.z);  Ws[wn][wkq + 3]  = f2tf32(fw.w);
        __syncthreads();

        if (t + 1 < nk) {
            const int k0 = (t + 1) * TBK;
            fa0 = (arow0 >= 0) ? __ldg((const float4*)(A + arow0 + k0 + akq)) : z4;
            fa1 = (arow1 >= 0) ? __ldg((const float4*)(A + arow1 + k0 + akq)) : z4;
            fw  = (wrow  >= 0) ? __ldg((const float4*)(W + wrow + k0 + wkq))  : z4;
        }

        #pragma unroll
        for (int ks = 0; ks < 2; ks++) {
            const int k0 = ks * 8;
            uint32_t a[2][4], b[4][2];
            #pragma unroll
            for (int mt = 0; mt < 2; mt++) {
                int rb = wm + mt * 16 + gid;
                a[mt][0] = As[rb][k0 + tig];
                a[mt][1] = As[rb + 8][k0 + tig];
                a[mt][2] = As[rb][k0 + tig + 4];
                a[mt][3] = As[rb + 8][k0 + tig + 4];
            }
            #pragma unroll
            for (int nt = 0; nt < 4; nt++) {
                int cb = wnn + nt * 8 + gid;
                b[nt][0] = Ws[cb][k0 + tig];
                b[nt][1] = Ws[cb][k0 + tig + 4];
            }
            #pragma unroll
            for (int mt = 0; mt < 2; mt++)
                #pragma unroll
                for (int nt = 0; nt < 4; nt++)
                    mma_tf32(acc[mt][nt], a[mt][0], a[mt][1], a[mt][2], a[mt][3],
                             b[nt][0], b[nt][1]);
        }
    }

    // epilogue: c0 -> (row, col), c1 -> (row, col+1), c2/c3 -> row+8
    #pragma unroll
    for (int mt = 0; mt < 2; mt++) {
        #pragma unroll
        for (int nt = 0; nt < 4; nt++) {
            int r0 = bm + wm + mt * 16 + gid;
            int c0 = bn + wnn + nt * 8 + 2 * tig;
            #pragma unroll
            for (int half = 0; half < 2; half++) {
                int r = r0 + half * 8;
                if (r >= M) continue;
                float v0 = acc[mt][nt][half * 2 + 0];
                float v1 = acc[mt][nt][half * 2 + 1];
                if (epi >= 1) {
                    if (c0 < N)     v0 += bias[c0];
                    if (c0 + 1 < N) v1 += bias[c0 + 1];
                }
                if (epi == 2) {
                    v0 = (v0 > 20.f) ? v0 : log1pf(expf(v0));
                    v1 = (v1 > 20.f) ? v1 : log1pf(expf(v1));
                }
                long long base = (long long)r * ldc + c0;
                if (c0 + 1 < N) {
                    *(float2*)&C[base] = make_float2(v0, v1);
                } else if (c0 < N) {
                    C[base] = v0;
                }
            }
        }
    }
}

// ---------------- fp32 NT SGEMM (kept for the precision-sensitive dt_proj) ----------------
#define BM 128
#define BN 64
#define BK 16
__global__ __launch_bounds__(256) void sgemm_nt(
    const float* __restrict__ A, const float* __restrict__ W,
    const float* __restrict__ bias, float* __restrict__ C,
    int M, int N, int K, int lda, int rpb, long long bsa,
    int ldc, int epi)
{
    __shared__ __align__(16) float As[BK][BM + 4];
    __shared__ __align__(16) float Ws[BK][BN + 4];
    const int tid = threadIdx.x;
    const int bm = blockIdx.x * BM, bn = blockIdx.y * BN;

    const int am0 = tid >> 2;
    const int am1 = am0 + 64;
    const int akq = (tid & 3) * 4;
    long long arow0 = -1, arow1 = -1;
    {
        int r0 = bm + am0;
        if (r0 < M) arow0 = (long long)(r0 / rpb) * bsa + (long long)(r0 % rpb) * lda;
        int r1 = bm + am1;
        if (r1 < M) arow1 = (long long)(r1 / rpb) * bsa + (long long)(r1 % rpb) * lda;
    }
    const int wn = tid >> 2;
    const int wkq = (tid & 3) * 4;
    long long wrow = -1;
    if (bn + wn < N) wrow = (long long)(bn + wn) * K;

    const float4 z4 = make_float4(0.f, 0.f, 0.f, 0.f);
    float4 fa0, fa1, fw;
    fa0 = (arow0 >= 0) ? __ldg((const float4*)(A + arow0 + akq)) : z4;
    fa1 = (arow1 >= 0) ? __ldg((const float4*)(A + arow1 + akq)) : z4;
    fw  = (wrow  >= 0) ? __ldg((const float4*)(W + wrow + wkq))  : z4;

    const int ty = tid >> 4, tx = tid & 15;
    const int m0 = ty * 8, n0 = tx * 4;
    float acc[8][4] = {};
    const int nk = K / BK;

    for (int t = 0; t < nk; t++) {
        __syncthreads();
        As[akq + 0][am0] = fa0.x; As[akq + 1][am0] = fa0.y;
        As[akq + 2][am0] = fa0.z; As[akq + 3][am0] = fa0.w;
        As[akq + 0][am1] = fa1.x; As[akq + 1][am1] = fa1.y;
        As[akq + 2][am1] = fa1.z; As[akq + 3][am1] = fa1.w;
        Ws[wkq + 0][wn]  = fw.x;  Ws[wkq + 1][wn]  = fw.y;
        Ws[wkq + 2][wn]  = fw.z;  Ws[wkq + 3][wn]  = fw.w;
        __syncthreads();

        if (t + 1 < nk) {
            const int k0 = (t + 1) * BK;
            fa0 = (arow0 >= 0) ? __ldg((const float4*)(A + arow0 + k0 + akq)) : z4;
            fa1 = (arow1 >= 0) ? __ldg((const float4*)(A + arow1 + k0 + akq)) : z4;
            fw  = (wrow  >= 0) ? __ldg((const float4*)(W + wrow + k0 + wkq))  : z4;
        }

        #pragma unroll
        for (int k = 0; k < BK; k++) {
            float4 a0 = *(const float4*)&As[k][m0];
            float4 a1 = *(const float4*)&As[k][m0 + 4];
            float4 w  = *(const float4*)&Ws[k][n0];
            float av[8] = {a0.x, a0.y, a0.z, a0.w, a1.x, a1.y, a1.z, a1.w};
            float wv[4] = {w.x, w.y, w.z, w.w};
            #pragma unroll
            for (int i = 0; i < 8; i++)
                #pragma unroll
                for (int j = 0; j < 4; j++)
                    acc[i][j] += av[i] * wv[j];
        }
    }

    #pragma unroll
    for (int i = 0; i < 8; i++) {
        int r = bm + m0 + i;
        if (r >= M) continue;
        float v[4];
        #pragma unroll
        for (int j = 0; j < 4; j++) {
            v[j] = acc[i][j];
            int c = bn + n0 + j;
            if (c < N && epi >= 1) v[j] += bias[c];
            if (epi == 2) v[j] = (v[j] > 20.f) ? v[j] : log1pf(expf(v[j]));
        }
        long long base = (long long)r * ldc + bn + n0;
        if (bn + n0 + 3 < N) {
            *(float4*)&C[base] = make_float4(v[0], v[1], v[2], v[3]);
        } else {
            #pragma unroll
            for (int j = 0; j < 4; j++)
                if (bn + n0 + j < N) C[base + j] = v[j];
        }
    }
}

// ---------------- cls token: u[b,0,:] = x[b,0,:] @ cls_w^T + cls_b + skip ----------------
__global__ void cls_kernel(const float* __restrict__ x, const float* __restrict__ cls_w,
                           const float* __restrict__ cls_b, const float* __restrict__ skip,
                           float* __restrict__ u)
{
    int b = blockIdx.x;
    int m = threadIdx.x;
    __shared__ float xs[DIM];
    for (int i = m; i < DIM; i += 256) xs[i] = x[(long long)b * 1025 * DIM + i];
    __syncthreads();
    float acc = 0.f;
    #pragma unroll 4
    for (int k = 0; k < DIM; k++) acc += xs[k] * cls_w[m * DIM + k];
    long long row = (long long)b * LSEQ;
    u[row * DM + m] = acc + cls_b[m] + skip[row * DM + m];
}

// ---------------- pixel-shuffle + LayerNorm + skip-add ----------------
__global__ void ln_expand_kernel(const float* __restrict__ e, const float* __restrict__ g,
                                 const float* __restrict__ bb, const float* __restrict__ skip,
                                 float* __restrict__ u)
{
    int o = blockIdx.x;                 // [0, 8192)
    int m = threadIdx.x;                // [0, 256)
    int b = o >> 12, rem = o & 4095;
    int t = rem >> 10, ti = rem & 1023;
    int q = ti & 1, w = (ti >> 1) & 15, p = (ti >> 5) & 1, h = ti >> 6;
    int n = h * 16 + w, pq = p * 2 + q;
    long long erow = (long long)((b * 4 + t) * 256 + n);
    float v = e[erow * 1024 + pq * 256 + m];
    __shared__ float red[8];
    float s = v;
    #pragma unroll
    for (int off = 16; off; off >>= 1) s += __shfl_xor_sync(~0u, s, off);
    if ((m & 31) == 0) red[m >> 5] = s;
    __syncthreads();
    float tot = 0.f;
    #pragma unroll
    for (int i = 0; i < 8; i++) tot += red[i];
    float mu = tot * (1.f / 256.f);
    __syncthreads();
    float dv = v - mu;
    s = dv * dv;
    #pragma unroll
    for (int off = 16; off; off >>= 1) s += __shfl_xor_sync(~0u, s, off);
    if ((m & 31) == 0) red[m >> 5] = s;
    __syncthreads();
    tot = 0.f;
    #pragma unroll
    for (int i = 0; i < 8; i++) tot += red[i];
    float var = tot * (1.f / 256.f);
    long long urow = (long long)b * LSEQ + 1 + t * 1024 + ti;
    u[urow * DM + m] = dv * rsqrtf(var + EPSV) * g[m] + bb[m] + skip[urow * DM + m];
}

// ---------------- depthwise causal conv (k=4) + silu ----------------
__global__ void conv_kernel(const float* __restrict__ xz, const float* __restrict__ cw,
                            const float* __restrict__ cb, float* __restrict__ xc)
{
    long long idx = (long long)blockIdx.x * 256 + threadIdx.x;
    if (idx >= (long long)NROWS * DIN) return;
    int d = (int)(idx & 511);
    long long r = idx >> 9;
    int b = (int)(r / LSEQ);
    int l = (int)(r % LSEQ);
    float acc = cb[d];
    #pragma unroll
    for (int k = 0; k < 4; k++) {
        int ls = l - 3 + k;
        if (ls >= 0) acc += cw[d * 4 + k] * xz[((long long)b * LSEQ + ls) * 1024 + d];
    }
    xc[idx] = acc / (1.f + __expf(-acc));
}

// ---------------- chunked scan, pass 1: local scans + decay products ----------------
__global__ void scan1_kernel(const float* __restrict__ delta, const float* __restrict__ xc,
                             const float* __restrict__ dbc, const float* __restrict__ A_log,
                             float* __restrict__ Aprod, float* __restrict__ Hloc)
{
    int gid = blockIdx.x * 16 + (threadIdx.x >> 4);
    int lane = threadIdx.x & 15;
    int d = gid % DIN;
    int rest = gid / DIN;
    int c = rest % NCH;
    int b = rest / NCH;
    float An = -expf(A_log[d * DST + lane]);
    float h = 0.f, ap = 1.f;
    int l0 = c * CHUNK;
    int lend = min(l0 + CHUNK, LSEQ);
    for (int l = l0; l < lend; l++) {
        long long row = (long long)b * LSEQ + l;
        float dl = delta[row * DIN + d];
        float xv = xc[row * DIN + d];
        float Bv = dbc[row * 48 + 16 + lane];
        float a = __expf(dl * An);
        h = h * a + dl * Bv * xv;
        ap *= a;
    }
    long long base = (((long long)b * DIN + d) * DST + lane) * NCH + c;
    Aprod[base] = ap;
    Hloc[base] = h;
}

// ---------------- pass 2: inter-chunk exclusive scan ----------------
__global__ void scan2_kernel(const float* __restrict__ Aprod, const float* __restrict__ Hloc,
                             float* __restrict__ Hinit)
{
    int i = blockIdx.x * 256 + threadIdx.x;
    if (i >= BSZ * DIN * DST) return;
    long long base = (long long)i * NCH;
    float h = 0.f;
    for (int c = 0; c < NCH; c++) {
        Hinit[base + c] = h;
        h = h * Aprod[base + c] + Hloc[base + c];
    }
}

// ---------------- pass 3: replay + fused output ----------------
__global__ void scan3_kernel(const float* __restrict__ delta, const float* __restrict__ xc,
                             const float* __restrict__ dbc, const float* __restrict__ A_log,
                             const float* __restrict__ Hinit, const float* __restrict__ xz,
                             const float* __restrict__ Dp, float* __restrict__ y)
{
    int gid = blockIdx.x * 16 + (threadIdx.x >> 4);
    int lane = threadIdx.x & 15;
    int d = gid % DIN;
    int rest = gid / DIN;
    int c = rest % NCH;
    int b = rest / NCH;
    float An = -expf(A_log[d * DST + lane]);
    float Dd = Dp[d];
    long long base = (((long long)b * DIN + d) * DST + lane) * NCH + c;
    float h = Hinit[base];
    int l0 = c * CHUNK;
    int lend = min(l0 + CHUNK, LSEQ);
    for (int l = l0; l < lend; l++) {
        long long row = (long long)b * LSEQ + l;
        float dl = delta[row * DIN + d];
        float xv = xc[row * DIN + d];
        float Bv = dbc[row * 48 + 16 + lane];
        float Cv = dbc[row * 48 + 32 + lane];
        float a = __expf(dl * An);
        h = h * a + dl * Bv * xv;
        float py = h * Cv;
        py += __shfl_xor_sync(~0u, py, 8, 16);
        py += __shfl_xor_sync(~0u, py, 4, 16);
        py += __shfl_xor_sync(~0u, py, 2, 16);
        py += __shfl_xor_sync(~0u, py, 1, 16);
        if (lane == 0) {
            float z = xz[row * 1024 + 512 + d];
            float sz = z / (1.f + __expf(-z));
            y[row * DIN + d] = (py + xv * Dd) * sz;
        }
    }
}

// ---------------- deterministic batchnorm ----------------
__global__ void bn_part_kernel(const float* __restrict__ u, float* __restrict__ part,
                               float* __restrict__ partsq)
{
    int blk = blockIdx.x;
    int m = threadIdx.x;
    int r0 = blk * 65;
    int r1 = min(r0 + 65, NROWS);
    float s = 0.f, q = 0.f;
    for (int r = r0; r < r1; r++) {
        float v = u[(long long)r * DM + m];
        s += v; q += v * v;
    }
    part[blk * DM + m] = s;
    partsq[blk * DM + m] = q;
}

__global__ void bn_final_kernel(const float* __restrict__ part, const float* __restrict__ partsq,
                                float* __restrict__ mean, float* __restrict__ var)
{
    int m = threadIdx.x;
    float s = 0.f, q = 0.f;
    for (int i = 0; i < 128; i++) { s += part[i * DM + m]; q += partsq[i * DM + m]; }
    float mu = s / (float)NROWS;
    mean[m] = mu;
    var[m] = q / (float)NROWS - mu * mu;
}

__global__ void bn_norm_kernel(const float* __restrict__ u, const float* __restrict__ mean,
                               const float* __restrict__ var, const float* __restrict__ g,
                               const float* __restrict__ bb, float* __restrict__ out,
                               long long out_size)
{
    long long idx = (long long)blockIdx.x * 256 + threadIdx.x;
    if (idx >= out_size) return;
    const long long NEL = (long long)NROWS * DM;
    if (idx < NEL) {
        int m = (int)(idx & 255);
        out[idx] = (u[idx] - mean[m]) * rsqrtf(var[m] + EPSV) * g[m] + bb[m];
    } else {
        out[idx] = 1024.0f;
    }
}

// ---------------- launch ----------------
extern "C" void kernel_launch(void* const* d_in, const int* in_sizes, int n_in,
                              void* d_out, int out_size)
{
    const float* x        = (const float*)d_in[0];
    const float* skip     = (const float*)d_in[1];
    const float* exp_w    = (const float*)d_in[2];
    const float* ln_g     = (const float*)d_in[3];
    const float* ln_b     = (const float*)d_in[4];
    const float* cls_w    = (const float*)d_in[5];
    const float* cls_b    = (const float*)d_in[6];
    const float* in_proj_w= (const float*)d_in[7];
    const float* conv_w   = (const float*)d_in[8];
    const float* conv_b   = (const float*)d_in[9];
    const float* xproj_w  = (const float*)d_in[10];
    const float* dt_w     = (const float*)d_in[11];
    const float* dt_b     = (const float*)d_in[12];
    const float* A_log    = (const float*)d_in[13];
    const float* Dp       = (const float*)d_in[14];
    const float* out_w    = (const float*)d_in[15];
    const float* bn_g     = (const float*)d_in[16];
    const float* bn_b     = (const float*)d_in[17];
    float* out = (float*)d_out;

    float *pe, *pu, *pu2, *pxz, *pxc, *pdbc, *pdelta, *py, *pAp, *pHl, *pHi;
    float *ppart, *ppartsq, *pmean, *pvar;
    cudaGetSymbolAddress((void**)&pe, g_e);
    cudaGetSymbolAddress((void**)&pu, g_u);
    cudaGetSymbolAddress((void**)&pu2, g_u2);
    cudaGetSymbolAddress((void**)&pxz, g_xz);
    cudaGetSymbolAddress((void**)&pxc, g_xc);
    cudaGetSymbolAddress((void**)&pdbc, g_dbc);
    cudaGetSymbolAddress((void**)&pdelta, g_delta);
    cudaGetSymbolAddress((void**)&py, g_y);
    cudaGetSymbolAddress((void**)&pAp, g_Ap);
    cudaGetSymbolAddress((void**)&pHl, g_Hl);
    cudaGetSymbolAddress((void**)&pHi, g_Hi);
    cudaGetSymbolAddress((void**)&ppart, g_part);
    cudaGetSymbolAddress((void**)&ppartsq, g_partsq);
    cudaGetSymbolAddress((void**)&pmean, g_mean);
    cudaGetSymbolAddress((void**)&pvar, g_var);

    // 1. cls token rows
    cls_kernel<<<2, 256>>>(x, cls_w, cls_b, skip, pu);

    // 2. expand GEMM (tf32): (2048,512) x (1024,512)^T -> g_e
    tc_gemm<<<dim3(16, 16), 256>>>(x + 512, exp_w, nullptr, pe,
                                   2048, 1024, 512, 512, 1024, (long long)1025 * 512, 1024, 0);

    // 3. pixel-shuffle + LN + skip
    ln_expand_kernel<<<8192, 256>>>(pe, ln_g, ln_b, skip, pu);

    float* uin = pu;
    float* uout = pu2;
    const int HUGE_RPB = 1 << 30;
    for (int layer = 0; layer < 2; layer++) {
        const float* Alog_l = A_log + (size_t)layer * DIN * DST;
        // in_proj (tf32): (8194,256) x (1024,256)^T -> xz
        tc_gemm<<<dim3(65, 16), 256>>>(uin, in_proj_w + (size_t)layer * 1024 * DM, nullptr, pxz,
                                       NROWS, 1024, DM, DM, HUGE_RPB, 0, 1024, 0);
        // depthwise conv + silu
        conv_kernel<<<16388, 256>>>(pxz, conv_w + (size_t)layer * DIN * 4,
                                    conv_b + (size_t)layer * DIN, pxc);
        // x_proj (tf32): (8194,512) x (48,512)^T -> dbc
        tc_gemm<<<dim3(65, 1), 256>>>(pxc, xproj_w + (size_t)layer * 48 * DIN, nullptr, pdbc,
                                      NROWS, 48, DIN, DIN, HUGE_RPB, 0, 48, 0);
        // delta (fp32, precision-sensitive): softplus(dt @ Wdt^T + bdt)
        sgemm_nt<<<dim3(65, 8), 256>>>(pdbc, dt_w + (size_t)layer * DIN * DTR,
                                       dt_b + (size_t)layer * DIN, pdelta,
                                       NROWS, DIN, DTR, 48, HUGE_RPB, 0, DIN, 2);
        // chunked selective scan
        scan1_kernel<<<4160, 256>>>(pdelta, pxc, pdbc, Alog_l, pAp, pHl);
        scan2_kernel<<<64, 256>>>(pAp, pHl, pHi);
        scan3_kernel<<<4160, 256>>>(pdelta, pxc, pdbc, Alog_l, pHi, pxz,
                                    Dp + (size_t)layer * DIN, py);
        // out_proj (tf32): (8194,512) x (256,512)^T -> uout
        tc_gemm<<<dim3(65, 4), 256>>>(py, out_w + (size_t)layer * DM * DIN, nullptr, uout,
                                      NROWS, DM, DIN, DIN, HUGE_RPB, 0, DM, 0);
        float* tmp = uin; uin = uout; uout = tmp;
    }

    // batchnorm (deterministic two-stage reduction)
    bn_part_kernel<<<128, 256>>>(uin, ppart, ppartsq);
    bn_final_kernel<<<1, 256>>>(ppart, ppartsq, pmean, pvar);
    long long nb = ((long long)out_size + 255) / 256;
    bn_norm_kernel<<<(int)nb, 256>>>(uin, pmean, pvar, bn_g, bn_b, out, (long long)out_size);
}